// round 15
// baseline (speedup 1.0000x reference)
#include <cuda_runtime.h>
#include <cuda_fp16.h>
#include <math.h>

#define DIN   128
#define DOUT  128
#define NB    2048
#define NU    20000
#define NMC   4
#define EPB   32
#define RES   0.9f

#define NBE   157           // ceil(20000/128) blocks for embed GEMM
#define LDA2  68            // A smem row stride in half2 words
#define LDWH  136           // W smem row stride in halfs (68 half2 words)

// Scratch
__device__ __half g_embed_h[NU * DOUT];       // [20000,128] fp16 embed @ Wv_agg
__device__ float  g_agg_all[NB * 3 * DOUT];   // [2048,384] = self_agg | K0 | Q0
__device__ float  g_ff_all [NB * 3 * DOUT];   // [2048,384] = self_ff  | K1 | Q1

__device__ __forceinline__ void mma_f16(float* c, const unsigned* a,
                                        unsigned b0, unsigned b1) {
    asm volatile(
        "mma.sync.aligned.m16n8k16.row.col.f32.f16.f16.f32 "
        "{%0,%1,%2,%3}, {%4,%5,%6,%7}, {%8,%9}, {%0,%1,%2,%3};\n"
        : "+f"(c[0]), "+f"(c[1]), "+f"(c[2]), "+f"(c[3])
        : "r"(a[0]), "r"(a[1]), "r"(a[2]), "r"(a[3]), "r"(b0), "r"(b1));
}

// ---------------------------------------------------------------------------
// Gather-GEMM, fp16 mma (m16n8k16), fp32 accumulate.
// Block: m128 x n128, K=128, 4 warps (warp = m32 x n128), 2 blocks/SM.
// Embed job (bx < NBE) writes fp16 output; self jobs write fp32.
// ---------------------------------------------------------------------------
__global__ __launch_bounds__(128, 2) void gemm_tc_kernel(
    const float* __restrict__ agg_table, const float* __restrict__ ff_table,
    const int* __restrict__ unique_ids,  const int* __restrict__ nodes,
    const float* __restrict__ Wv_agg, const float* __restrict__ Wv_ff,
    const float* __restrict__ Wk,     const float* __restrict__ Wq)
{
    extern __shared__ unsigned smem[];
    unsigned* As = smem;                    // [128][LDA2] half2 words
    unsigned* Ws = smem + 128 * LDA2;       // [128][LDWH/2] half2 words

    // job decode
    const float* table; const int* idx; const float* W; float* out;
    int M, ldout, col0, row0, embed_job;
    int bx = blockIdx.x;
    if (bx < NBE) {
        embed_job = 1;
        table = agg_table; idx = unique_ids; W = Wv_agg; out = nullptr;
        M = NU; ldout = DOUT; col0 = 0; row0 = bx * 128;
    } else {
        embed_job = 0;
        int b = bx - NBE;
        int grp = b / 48;            // 0: agg, 1: ff
        int b2 = b % 48;
        int wsel = b2 / 16, mb = b2 % 16;
        table = grp ? ff_table : agg_table;
        idx = nodes;
        W = (wsel == 0) ? (grp ? Wv_ff : Wv_agg) : (wsel == 1 ? Wk : Wq);
        out = grp ? g_ff_all : g_agg_all;
        M = NB; ldout = 3 * DOUT; col0 = wsel * 128; row0 = mb * 128;
    }

    const int lane = threadIdx.x & 31;
    const int warp = threadIdx.x >> 5;
    const int g  = lane >> 2;
    const int tg = lane & 3;
    const int wr0 = warp * 32;

    // prefetch this warp's 32 row indices
    int myrow = row0 + wr0 + lane;
    myrow = (myrow < M) ? myrow : (M - 1);
    const int myidx = __ldg(idx + myrow);

    // stage A rows first (long-latency gathers, independent addresses)
    #pragma unroll
    for (int e = 0; e < 32; e++) {
        int ridx = __shfl_sync(0xffffffffu, myidx, e);
        float4 x = __ldcg((const float4*)(table + (long)ridx * DIN + lane * 4));
        __half2 h01 = __floats2half2_rn(x.x, x.y);
        __half2 h23 = __floats2half2_rn(x.z, x.w);
        *(uint2*)(As + (wr0 + e) * LDA2 + lane * 2) =
            make_uint2(*(unsigned*)&h01, *(unsigned*)&h23);
    }

    // stage W rows [wr0, wr0+32)
    #pragma unroll
    for (int i = 0; i < 32; i++) {
        int row = wr0 + i;
        float4 v = *(const float4*)(W + row * 128 + lane * 4);
        __half2 h01 = __floats2half2_rn(v.x, v.y);
        __half2 h23 = __floats2half2_rn(v.z, v.w);
        *(uint2*)(Ws + row * (LDWH / 2) + lane * 2) =
            make_uint2(*(unsigned*)&h01, *(unsigned*)&h23);
    }
    __syncthreads();

    unsigned ws_s;
    {
        unsigned long long p;
        asm("cvta.to.shared.u64 %0, %1;" : "=l"(p) : "l"((const void*)Ws));
        ws_s = (unsigned)p;
    }

    float acc[2][16][4];
    #pragma unroll
    for (int mt = 0; mt < 2; mt++)
        #pragma unroll
        for (int j = 0; j < 16; j++)
            #pragma unroll
            for (int q = 0; q < 4; q++) acc[mt][j][q] = 0.f;

    const int lgrp = lane >> 3;
    const int lrow = lane & 7;
    const int kofs = (lgrp & 1) * 8 + lrow;
    const int nofs = (lgrp >> 1) * 8;

    #pragma unroll
    for (int kk = 0; kk < 8; kk++) {     // k16 chunks
        unsigned a[2][4];
        #pragma unroll
        for (int mt = 0; mt < 2; mt++) {
            const unsigned* ab = As + (wr0 + mt * 16) * LDA2 + kk * 8;
            a[mt][0] = ab[g * LDA2 + tg];
            a[mt][1] = ab[(g + 8) * LDA2 + tg];
            a[mt][2] = ab[g * LDA2 + 4 + tg];
            a[mt][3] = ab[(g + 8) * LDA2 + 4 + tg];
        }
        unsigned rowaddr = ws_s + ((kk * 16 + kofs) * LDWH + nofs) * 2;
        #pragma unroll
        for (int jj = 0; jj < 8; jj++) { // n16 chunks
            unsigned b0, b1, b2, b3;
            asm volatile(
                "ldmatrix.sync.aligned.m8n8.x4.trans.shared.b16 "
                "{%0,%1,%2,%3}, [%4];"
                : "=r"(b0), "=r"(b1), "=r"(b2), "=r"(b3)
                : "r"(rowaddr + jj * 32));
            mma_f16(acc[0][2 * jj],     a[0], b0, b1);
            mma_f16(acc[0][2 * jj + 1], a[0], b2, b3);
            mma_f16(acc[1][2 * jj],     a[1], b0, b1);
            mma_f16(acc[1][2 * jj + 1], a[1], b2, b3);
        }
    }

    // epilogue
    #pragma unroll
    for (int mt = 0; mt < 2; mt++) {
        int rbase = row0 + wr0 + mt * 16;
        #pragma unroll
        for (int j = 0; j < 16; j++) {
            int c = col0 + j * 8 + 2 * tg;
            int r0g = rbase + g;
            int r1g = rbase + 8 + g;
            if (embed_job) {
                if (r0g < M)
                    *(__half2*)(g_embed_h + (long)r0g * DOUT + c) =
                        __floats2half2_rn(acc[mt][j][0], acc[mt][j][1]);
                if (r1g < M)
                    *(__half2*)(g_embed_h + (long)r1g * DOUT + c) =
                        __floats2half2_rn(acc[mt][j][2], acc[mt][j][3]);
            } else {
                *(float2*)(out + (long)r0g * ldout + c) =
                    make_float2(acc[mt][j][0], acc[mt][j][1]);
                *(float2*)(out + (long)r1g * ldout + c) =
                    make_float2(acc[mt][j][2], acc[mt][j][3]);
            }
        }
    }
}

// ---------------------------------------------------------------------------
// Finalize: warp-per-node (4/block). Software-pipelined:
//   batch0 loads (16) -> dedup under them -> batch1 loads (16) ->
//   acc batch0 -> epilogue-input loads -> acc batch1 -> dots -> epilogue.
// Uniform-branch accumulation (4 adds/edge, dups skipped). Fast-math.
// ---------------------------------------------------------------------------
#define NRED 14
__global__ __launch_bounds__(128, 4) void finalize_kernel(
    const int* __restrict__ layer_idx, const int* __restrict__ col_idx,
    const float* __restrict__ mu_w, float* __restrict__ out)
{
    const int lane = threadIdx.x & 31;
    const int warp = threadIdx.x >> 5;
    const int n = blockIdx.x * 4 + warp;

    int lay = layer_idx[n * EPB + lane];
    int col = col_idx[n * EPB + lane];

    // ---- batch 0: issue 16 gather loads immediately (only need col) ----
    uint2 v0[16];
    #pragma unroll
    for (int e = 0; e < 16; e++) {
        int ce = __shfl_sync(0xffffffffu, col, e);
        v0[e] = __ldcg((const uint2*)(g_embed_h + (long)ce * DOUT + lane * 4));
    }

    // ---- dedup while batch 0 is in flight ----
    int key = (lay << 15) | col;                 // col < 20000 < 2^15
    unsigned mm = __match_any_sync(0xffffffffu, key);
    bool valid = ((mm & ((1u << lane) - 1u)) == 0u);
    int vm = valid ? lay : -1;
    float cnt[NMC];
    cnt[0] = (float)__popc(__ballot_sync(0xffffffffu, valid && lay == 0));
    cnt[1] = (float)__popc(__ballot_sync(0xffffffffu, valid && lay == 1));
    cnt[2] = (float)__popc(__ballot_sync(0xffffffffu, valid && lay == 2));
    cnt[3] = (float)__popc(__ballot_sync(0xffffffffu, valid && lay == 3));

    // ---- batch 1: issue next 16 loads ----
    uint2 v1[16];
    #pragma unroll
    for (int e = 0; e < 16; e++) {
        int ce = __shfl_sync(0xffffffffu, col, 16 + e);
        v1[e] = __ldcg((const uint2*)(g_embed_h + (long)ce * DOUT + lane * 4));
    }

    float4 nb[NMC];
    #pragma unroll
    for (int m = 0; m < NMC; m++) nb[m] = make_float4(0.f, 0.f, 0.f, 0.f);

    #define ACC_EDGE(vv, eidx) do { \
        int me = __shfl_sync(0xffffffffu, vm, (eidx)); \
        if (me >= 0) { \
            float2 f01 = __half22float2(*(__half2*)&(vv).x); \
            float2 f23 = __half22float2(*(__half2*)&(vv).y); \
            if (me == 0) { nb[0].x += f01.x; nb[0].y += f01.y; nb[0].z += f23.x; nb[0].w += f23.y; } \
            else if (me == 1) { nb[1].x += f01.x; nb[1].y += f01.y; nb[1].z += f23.x; nb[1].w += f23.y; } \
            else if (me == 2) { nb[2].x += f01.x; nb[2].y += f01.y; nb[2].z += f23.x; nb[2].w += f23.y; } \
            else { nb[3].x += f01.x; nb[3].y += f01.y; nb[3].z += f23.x; nb[3].w += f23.y; } \
        } \
    } while (0)

    // ---- accumulate batch 0 (frees v0 registers) ----
    #pragma unroll
    for (int e = 0; e < 16; e++) ACC_EDGE(v0[e], e);

    // ---- epilogue-input loads fly while batch 1 is consumed ----
    const float* ar = g_agg_all + (long)n * (3 * DOUT);
    const float* fr = g_ff_all  + (long)n * (3 * DOUT);
    float4 sa  = *(const float4*)(ar + lane * 4);
    float4 k0  = *(const float4*)(ar + DOUT + lane * 4);
    float4 q0  = *(const float4*)(ar + 2 * DOUT + lane * 4);
    float4 sff = *(const float4*)(fr + lane * 4);
    float4 k1  = *(const float4*)(fr + DOUT + lane * 4);
    float4 q1  = *(const float4*)(fr + 2 * DOUT + lane * 4);
    float4 mu0 = *(const float4*)(mu_w + lane * 4);
    float4 mu1 = *(const float4*)(mu_w + DOUT + lane * 4);

    // ---- accumulate batch 1 ----
    #pragma unroll
    for (int e = 0; e < 16; e++) ACC_EDGE(v1[e], 16 + e);

    #pragma unroll
    for (int m = 0; m < NMC; m++) {
        float inv = __fdividef(1.f, fmaxf(cnt[m], 1.f));
        nb[m].x *= inv; nb[m].y *= inv; nb[m].z *= inv; nb[m].w *= inv;
    }

    #define DOT4(a, b) ((a).x*(b).x + (a).y*(b).y + (a).z*(b).z + (a).w*(b).w)
    float p[NRED];
    p[0]  = DOT4(sa, sa);       p[1]  = DOT4(sa, mu0);
    p[2]  = DOT4(nb[0], nb[0]); p[3]  = DOT4(nb[0], mu1);
    p[4]  = DOT4(nb[1], nb[1]); p[5]  = DOT4(nb[1], mu1);
    p[6]  = DOT4(nb[2], nb[2]); p[7]  = DOT4(nb[2], mu1);
    p[8]  = DOT4(nb[3], nb[3]); p[9]  = DOT4(nb[3], mu1);
    p[10] = DOT4(k0, q0); p[11] = DOT4(k0, q1);
    p[12] = DOT4(k1, q0); p[13] = DOT4(k1, q1);

    #pragma unroll
    for (int o = 16; o > 0; o >>= 1)
        #pragma unroll
        for (int i = 0; i < NRED; i++)
            p[i] += __shfl_xor_sync(0xffffffffu, p[i], o);

    // persona softmax (fast math)
    float logit[NMC];
    #pragma unroll
    for (int m = 0; m < NMC; m++)
        logit[m] = (p[1] + p[3 + 2 * m]) * __frsqrt_rn(fmaxf(p[0] + p[2 + 2 * m], 1e-24f));
    float mx = fmaxf(fmaxf(logit[0], logit[1]), fmaxf(logit[2], logit[3]));
    float ex[NMC], es = 0.f;
    #pragma unroll
    for (int m = 0; m < NMC; m++) { ex[m] = __expf(logit[m] - mx); es += ex[m]; }
    float ies = __fdividef(1.f, es);
    float4 nsum = make_float4(0.f, 0.f, 0.f, 0.f);
    #pragma unroll
    for (int m = 0; m < NMC; m++) {
        float c = ex[m] * ies;
        nsum.x = fmaf(c, nb[m].x, nsum.x); nsum.y = fmaf(c, nb[m].y, nsum.y);
        nsum.z = fmaf(c, nb[m].z, nsum.z); nsum.w = fmaf(c, nb[m].w, nsum.w);
    }
    float4 va = make_float4(0.5f * (sa.x + nsum.x), 0.5f * (sa.y + nsum.y),
                            0.5f * (sa.z + nsum.z), 0.5f * (sa.w + nsum.w));

    // 2x2 highway attention
    float s00 = p[10] * (1.f / 128.f), s01 = p[11] * (1.f / 128.f);
    float s10 = p[12] * (1.f / 128.f), s11 = p[13] * (1.f / 128.f);
    float m0 = fmaxf(s00, s01), m1 = fmaxf(s10, s11);
    float e00 = __expf(s00 - m0), e01 = __expf(s01 - m0);
    float e10 = __expf(s10 - m1), e11 = __expf(s11 - m1);
    float i0 = __fdividef(1.f, e00 + e01);
    float i1 = __fdividef(1.f, e10 + e11);
    float w00 = e00 * i0, w01 = e01 * i0;
    float w10 = e10 * i1, w11 = e11 * i1;

    float4 o0, o1;
    #define FIN(comp) do { \
        float nv0 = w00 * va.comp + w01 * sff.comp; \
        float nv1 = w10 * va.comp + w11 * sff.comp; \
        float a0 = RES * va.comp  + (1.f - RES) * nv0; \
        float a1 = RES * sff.comp + (1.f - RES) * nv1; \
        o0.comp = (a0 > 0.f) ? a0 : (__expf(a0) - 1.f); \
        o1.comp = (a1 > 0.f) ? a1 : (__expf(a1) - 1.f); \
    } while (0)
    FIN(x); FIN(y); FIN(z); FIN(w);

    *(float4*)(out + (long)n * DOUT + lane * 4) = o0;
    *(float4*)(out + (long)NB * DOUT + (long)n * DOUT + lane * 4) = o1;
}

// ---------------------------------------------------------------------------
extern "C" void kernel_launch(void* const* d_in, const int* in_sizes, int n_in,
                              void* d_out, int out_size)
{
    const int*   nodes      = (const int*)  d_in[0];
    const int*   unique_ids = (const int*)  d_in[1];
    // d_in[2] = row_idx: repeat(arange(B), 32) — implicit
    const int*   layer_idx  = (const int*)  d_in[3];
    const int*   col_idx    = (const int*)  d_in[4];
    const float* agg_table  = (const float*)d_in[5];
    const float* ff_table   = (const float*)d_in[6];
    const float* Wv_agg     = (const float*)d_in[7];
    const float* Wv_ff      = (const float*)d_in[8];
    const float* Wk         = (const float*)d_in[9];
    const float* Wq         = (const float*)d_in[10];
    const float* mu_w       = (const float*)d_in[11];
    float* out = (float*)d_out;

    const int smem_bytes = (128 * LDA2 + 128 * (LDWH / 2)) * (int)sizeof(unsigned);
    cudaFuncSetAttribute(gemm_tc_kernel,
                         cudaFuncAttributeMaxDynamicSharedMemorySize, smem_bytes);

    gemm_tc_kernel<<<NBE + 96, 128, smem_bytes>>>(
        agg_table, ff_table, unique_ids, nodes, Wv_agg, Wv_ff, Wk, Wq);

    finalize_kernel<<<NB / 4, 128>>>(layer_idx, col_idx, mu_w, out);
}